// round 5
// baseline (speedup 1.0000x reference)
#include <cuda_runtime.h>
#include <cstddef>

#define Bb 8
#define Tt 2048
#define Dd 512
#define Hh 512
#define FOURH 2048
#define GRID_R 128

typedef unsigned long long u64;

// ---------------- scratch (static device globals: allocation-free) ----------------
__device__ float g_wx[(size_t)Bb * Tt * FOURH];   // 128 MiB: precomputed x @ W^T + b
__device__ float g_h[2][Bb * Hh];                 // double-buffered hidden state
__device__ unsigned g_flag[GRID_R];               // per-block monotonic epoch flags (no reset)

// ---------------- packed f32x2 helpers (b64 regs via "l" constraint) ----------------
__device__ __forceinline__ void fma2(u64 &acc, u64 a, u64 b) {
    asm("fma.rn.f32x2 %0, %1, %2, %0;" : "+l"(acc) : "l"(a), "l"(b));
}
__device__ __forceinline__ u64 dup2(float s) {
    u64 d; asm("mov.b64 %0, {%1, %1};" : "=l"(d) : "f"(s)); return d;
}
__device__ __forceinline__ void unpack2(u64 v, float &lo, float &hi) {
    asm("mov.b64 {%0, %1}, %2;" : "=f"(lo), "=f"(hi) : "l"(v));
}

// ---------------- scoped sync primitives (distinct-address, no atomics) ----------------
__device__ __forceinline__ void st_release_u32(unsigned* p, unsigned v) {
    asm volatile("st.release.gpu.global.u32 [%0], %1;" :: "l"(p), "r"(v) : "memory");
}
__device__ __forceinline__ void fence_acq() {
    asm volatile("fence.acq_rel.gpu;" ::: "memory");
}

// ---------------- fast gate math (MUFU-based, ~1e-7 rel err) ----------------
__device__ __forceinline__ float sigm_f(float x) {
    return __fdividef(1.f, 1.f + __expf(-x));
}
__device__ __forceinline__ float tanh_f(float x) {
    float e = __expf(2.f * x);
    return 1.f - __fdividef(2.f, e + 1.f);
}

// =====================================================================
// Kernel 1: Wx = x[16384,512] @ W_w[2048,512]^T + W_b  -> g_wx[16384,2048]
// 128x128x32 tiles, 256 threads, 8x8 microtile on fma.rn.f32x2
// =====================================================================
__global__ void __launch_bounds__(256) gemm_wx_kernel(
    const float* __restrict__ x, const float* __restrict__ Ww,
    const float* __restrict__ Wb)
{
    __shared__ __align__(16) float a_s[32][132];
    __shared__ __align__(16) float b_s[32][132];

    const int tid = threadIdx.x;
    const int tx = tid & 15, ty = tid >> 4;
    const int m0 = blockIdx.y * 128, n0 = blockIdx.x * 128;

    u64 acc[8][4];
    #pragma unroll
    for (int i = 0; i < 8; i++)
        #pragma unroll
        for (int j = 0; j < 4; j++) acc[i][j] = 0ull;

    const int lr = tid >> 3;
    const int kq = (tid & 7) * 4;

    for (int kc = 0; kc < 512; kc += 32) {
        __syncthreads();
        #pragma unroll
        for (int i = 0; i < 4; i++) {
            int r = lr + 32 * i;
            float4 av = *(const float4*)&x[(size_t)(m0 + r) * 512 + kc + kq];
            a_s[kq + 0][r] = av.x; a_s[kq + 1][r] = av.y;
            a_s[kq + 2][r] = av.z; a_s[kq + 3][r] = av.w;
            float4 bv = *(const float4*)&Ww[(size_t)(n0 + r) * 512 + kc + kq];
            b_s[kq + 0][r] = bv.x; b_s[kq + 1][r] = bv.y;
            b_s[kq + 2][r] = bv.z; b_s[kq + 3][r] = bv.w;
        }
        __syncthreads();
        #pragma unroll
        for (int k = 0; k < 32; k++) {
            float4 af0 = *(const float4*)&a_s[k][ty * 8];
            float4 af1 = *(const float4*)&a_s[k][ty * 8 + 4];
            ulonglong2 b01 = *(const ulonglong2*)&b_s[k][tx * 8];
            ulonglong2 b23 = *(const ulonglong2*)&b_s[k][tx * 8 + 4];
            u64 ad[8];
            ad[0] = dup2(af0.x); ad[1] = dup2(af0.y); ad[2] = dup2(af0.z); ad[3] = dup2(af0.w);
            ad[4] = dup2(af1.x); ad[5] = dup2(af1.y); ad[6] = dup2(af1.z); ad[7] = dup2(af1.w);
            #pragma unroll
            for (int i = 0; i < 8; i++) {
                fma2(acc[i][0], ad[i], b01.x);
                fma2(acc[i][1], ad[i], b01.y);
                fma2(acc[i][2], ad[i], b23.x);
                fma2(acc[i][3], ad[i], b23.y);
            }
        }
    }

    float wb[8];
    #pragma unroll
    for (int j = 0; j < 8; j++) wb[j] = Wb[n0 + tx * 8 + j];

    #pragma unroll
    for (int i = 0; i < 8; i++) {
        float o[8];
        #pragma unroll
        for (int jp = 0; jp < 4; jp++) {
            float lo, hi; unpack2(acc[i][jp], lo, hi);
            o[jp * 2]     = lo + wb[jp * 2];
            o[jp * 2 + 1] = hi + wb[jp * 2 + 1];
        }
        size_t row = (size_t)(m0 + ty * 8 + i);
        float4* dst = (float4*)&g_wx[row * FOURH + n0 + tx * 8];
        dst[0] = make_float4(o[0], o[1], o[2], o[3]);
        dst[1] = make_float4(o[4], o[5], o[6], o[7]);
    }
}

// ---------------- multi-value warp butterfly reduce ----------------
#define RED_ROUND(HALF) { \
    const bool up_ = (lane & HALF) != 0; \
    _Pragma("unroll") \
    for (int i_ = 0; i_ < HALF; i_++) { \
        float a_ = v[i_], b_ = v[i_ + HALF]; \
        float mine_ = up_ ? b_ : a_; \
        float oth_  = up_ ? a_ : b_; \
        float rc_ = __shfl_xor_sync(0xffffffffu, oth_, HALF); \
        v[i_] = mine_ + rc_; } }

// =====================================================================
// Kernel 2: persistent recurrent sLSTM. 128 blocks x 512 threads (16 warps).
// Block b owns hidden units [4b, 4b+4).
// Warp w: gate g = w>>2, k-quarter q = w&3 (128 columns).
// Barrier = per-block epoch flags (distinct L2 addresses, zero atomic serialization).
// =====================================================================
__global__ void __launch_bounds__(512) lstm_rec_kernel(
    const float* __restrict__ Uw, const float* __restrict__ Ub,
    const float* __restrict__ alpha, float* __restrict__ out)
{
    __shared__ __align__(16) float h_s[Bb][Hh];   // 16 KB staged hidden state
    __shared__ float z_s[16][32];                 // per-warp partial dots

    const int tid  = threadIdx.x;
    const int w    = tid >> 5;
    const int lane = tid & 31;
    const int g    = w >> 2;       // gate
    const int q    = w & 3;        // k-quarter (128 cols)
    const int blk  = blockIdx.x;
    const int j0   = blk * 4;

    // epoch base: own flag's value at entry (uniform across blocks after any full run)
    const unsigned base = __ldcg(&g_flag[blk]);

    // U_w rows register-resident: warp (g,q), local row j, lane cols 128q+4lane..+3
    ulonglong2 u[4];
    #pragma unroll
    for (int j = 0; j < 4; j++)
        u[j] = *(const ulonglong2*)&Uw[(size_t)(g * Hh + j0 + j) * Hh + 128 * q + 4 * lane];

    const int bb = lane & 7;       // batch for finalize lane
    const int jl = lane >> 3;      // local hidden unit for finalize lane
    float c_st = 0.f, alpha_r = 0.f;
    float ub_r[4] = {0.f, 0.f, 0.f, 0.f};
    if (w == 0) {
        #pragma unroll
        for (int gg = 0; gg < 4; gg++) ub_r[gg] = Ub[gg * Hh + j0 + jl];
        alpha_r = alpha[j0 + jl];
    }

    // publish h0 = 0 (warp 0 zeroes this block's 32-float slice, then releases epoch+1)
    if (w == 0) {
        g_h[0][blk * 32 + lane] = 0.f;
        __syncwarp();
        if (lane == 0) st_release_u32(&g_flag[blk], base + 1u);
    }

    for (int t = 0; t < Tt; ++t) {
        // prefetch Wx_t (independent of h -> overlaps flag wait + DRAM latency)
        float wx[4];
        if (w == 0) {
            const float* wp = &g_wx[((size_t)bb * Tt + t) * FOURH + j0 + jl];
            #pragma unroll
            for (int gg = 0; gg < 4; gg++) wx[gg] = __ldg(wp + gg * Hh);

            // wait: all 128 per-block flags reached epoch base + t + 1
            const unsigned tgt = (unsigned)(t + 1);
            const uint4* fp = (const uint4*)&g_flag[lane * 4];
            int spins = 0;
            for (;;) {
                uint4 f = __ldcg(fp);
                bool ok = (f.x - base >= tgt) & (f.y - base >= tgt) &
                          (f.z - base >= tgt) & (f.w - base >= tgt);
                if (__all_sync(0xffffffffu, ok)) break;
                if (++spins > 512) __nanosleep(32);
            }
            fence_acq();
        }
        __syncthreads();

        // stage h_t into smem (L2-only loads; keep g_h out of L1 entirely)
        {
            const float4* src = (const float4*)g_h[t & 1];
            float4* dst = (float4*)&h_s[0][0];
            dst[tid]       = __ldcg(&src[tid]);
            dst[tid + 512] = __ldcg(&src[tid + 512]);
        }
        __syncthreads();

        // partial dots: 4 rows x 8 batches over this warp's 128 columns
        u64 acc[4][8];
        #pragma unroll
        for (int j = 0; j < 4; j++)
            #pragma unroll
            for (int b = 0; b < 8; b++) acc[j][b] = 0ull;
        #pragma unroll
        for (int b = 0; b < 8; b++) {
            ulonglong2 h2 = *(const ulonglong2*)&h_s[b][128 * q + 4 * lane];
            #pragma unroll
            for (int j = 0; j < 4; j++) fma2(acc[j][b], u[j].x, h2.x);
            #pragma unroll
            for (int j = 0; j < 4; j++) fma2(acc[j][b], u[j].y, h2.y);
        }

        // collapse pair halves, then 32-value butterfly:
        // lane L ends with this warp's 128-col partial of dot(j=L>>3, b=L&7)
        float v[32];
        #pragma unroll
        for (int j = 0; j < 4; j++)
            #pragma unroll
            for (int b = 0; b < 8; b++) {
                float lo, hi; unpack2(acc[j][b], lo, hi);
                v[j * 8 + b] = lo + hi;
            }
        RED_ROUND(16) RED_ROUND(8) RED_ROUND(4) RED_ROUND(2) RED_ROUND(1)
        z_s[w][lane] = v[0];
        __syncthreads();

        // gate math + state update (warp 0; c lives in registers)
        if (w == 0) {
            float zi = z_s[0][lane]  + z_s[1][lane]  + z_s[2][lane]  + z_s[3][lane]
                     + wx[0] + ub_r[0];
            float zf = z_s[4][lane]  + z_s[5][lane]  + z_s[6][lane]  + z_s[7][lane]
                     + wx[1] + ub_r[1];
            float zo = z_s[8][lane]  + z_s[9][lane]  + z_s[10][lane] + z_s[11][lane]
                     + wx[2] + ub_r[2];
            float zg = z_s[12][lane] + z_s[13][lane] + z_s[14][lane] + z_s[15][lane]
                     + wx[3] + ub_r[3];
            float ig = sigm_f(zi), fg = sigm_f(zf), og = sigm_f(zo);
            float gg = tanh_f(zg);
            c_st = alpha_r * (fg * c_st + ig * gg);
            float hv = og * tanh_f(c_st);

            // publish h_{t+1}, then release this block's epoch flag
            g_h[(t + 1) & 1][bb * Hh + j0 + jl] = hv;
            __syncwarp();
            if (lane == 0) st_release_u32(&g_flag[blk], base + (unsigned)(t + 2));

            // off-critical-path stores (kernel-end fence covers visibility)
            out[((size_t)bb * Tt + t) * Hh + j0 + jl] = hv;
            if (t == Tt - 1) {
                out[(size_t)Bb * Tt * Hh + bb * Hh + j0 + jl] = hv;                      // final h
                out[(size_t)Bb * Tt * Hh + (size_t)Bb * Hh + bb * Hh + j0 + jl] = c_st;  // final c
            }
        }
    }
    // flags are monotonic epochs: no reset needed; all blocks end at base + Tt + 1.
}

// =====================================================================
extern "C" void kernel_launch(void* const* d_in, const int* in_sizes, int n_in,
                              void* d_out, int out_size)
{
    const float* x     = (const float*)d_in[0];
    const float* Ww    = (const float*)d_in[1];
    const float* Wb    = (const float*)d_in[2];
    const float* Uw    = (const float*)d_in[3];
    const float* Ub    = (const float*)d_in[4];
    const float* alpha = (const float*)d_in[5];
    float* out = (float*)d_out;

    dim3 ggrid(FOURH / 128, (Bb * Tt) / 128);   // 16 x 128
    gemm_wx_kernel<<<ggrid, 256>>>(x, Ww, Wb);
    lstm_rec_kernel<<<GRID_R, 512>>>(Uw, Ub, alpha, out);
}

// round 6
// speedup vs baseline: 1.8943x; 1.8943x over previous
#include <cuda_runtime.h>
#include <cstddef>

#define Bb 8
#define Tt 2048
#define Dd 512
#define Hh 512
#define FOURH 2048
#define GRID_R 128

typedef unsigned long long u64;

// ---------------- scratch (static device globals: allocation-free) ----------------
__device__ float g_wx[(size_t)Bb * Tt * FOURH];   // 128 MiB: precomputed x @ W^T + b
__device__ float g_h[2][Bb * Hh];                 // double-buffered hidden state
__device__ unsigned g_bar;                        // monotonic grid barrier counter (self-resetting)

// ---------------- packed f32x2 helpers (b64 regs via "l" constraint) ----------------
__device__ __forceinline__ void fma2(u64 &acc, u64 a, u64 b) {
    asm("fma.rn.f32x2 %0, %1, %2, %0;" : "+l"(acc) : "l"(a), "l"(b));
}
__device__ __forceinline__ u64 dup2(float s) {
    u64 d; asm("mov.b64 %0, {%1, %1};" : "=l"(d) : "f"(s)); return d;
}
__device__ __forceinline__ void unpack2(u64 v, float &lo, float &hi) {
    asm("mov.b64 {%0, %1}, %2;" : "=f"(lo), "=f"(hi) : "l"(v));
}

// ---------------- scoped sync primitives ----------------
__device__ __forceinline__ void bar_arrive_release() {
    asm volatile("red.release.gpu.global.add.u32 [%0], %1;"
                 :: "l"(&g_bar), "r"(1u) : "memory");
}
__device__ __forceinline__ unsigned bar_peek_acquire() {
    unsigned v;
    asm volatile("ld.acquire.gpu.global.u32 %0, [%1];"
                 : "=r"(v) : "l"(&g_bar) : "memory");
    return v;
}

// ---------------- fast gate math (MUFU-based, ~1e-7 rel err) ----------------
__device__ __forceinline__ float sigm_f(float x) {
    return __fdividef(1.f, 1.f + __expf(-x));
}
__device__ __forceinline__ float tanh_f(float x) {
    float e = __expf(2.f * x);
    return 1.f - __fdividef(2.f, e + 1.f);
}

// =====================================================================
// Kernel 1: Wx = x[16384,512] @ W_w[2048,512]^T + W_b  -> g_wx[16384,2048]
// 128x128x32 tiles, 256 threads, 8x8 microtile on fma.rn.f32x2
// =====================================================================
__global__ void __launch_bounds__(256) gemm_wx_kernel(
    const float* __restrict__ x, const float* __restrict__ Ww,
    const float* __restrict__ Wb)
{
    __shared__ __align__(16) float a_s[32][132];
    __shared__ __align__(16) float b_s[32][132];

    const int tid = threadIdx.x;
    const int tx = tid & 15, ty = tid >> 4;
    const int m0 = blockIdx.y * 128, n0 = blockIdx.x * 128;

    u64 acc[8][4];
    #pragma unroll
    for (int i = 0; i < 8; i++)
        #pragma unroll
        for (int j = 0; j < 4; j++) acc[i][j] = 0ull;

    const int lr = tid >> 3;
    const int kq = (tid & 7) * 4;

    for (int kc = 0; kc < 512; kc += 32) {
        __syncthreads();
        #pragma unroll
        for (int i = 0; i < 4; i++) {
            int r = lr + 32 * i;
            float4 av = *(const float4*)&x[(size_t)(m0 + r) * 512 + kc + kq];
            a_s[kq + 0][r] = av.x; a_s[kq + 1][r] = av.y;
            a_s[kq + 2][r] = av.z; a_s[kq + 3][r] = av.w;
            float4 bv = *(const float4*)&Ww[(size_t)(n0 + r) * 512 + kc + kq];
            b_s[kq + 0][r] = bv.x; b_s[kq + 1][r] = bv.y;
            b_s[kq + 2][r] = bv.z; b_s[kq + 3][r] = bv.w;
        }
        __syncthreads();
        #pragma unroll
        for (int k = 0; k < 32; k++) {
            float4 af0 = *(const float4*)&a_s[k][ty * 8];
            float4 af1 = *(const float4*)&a_s[k][ty * 8 + 4];
            ulonglong2 b01 = *(const ulonglong2*)&b_s[k][tx * 8];
            ulonglong2 b23 = *(const ulonglong2*)&b_s[k][tx * 8 + 4];
            u64 ad[8];
            ad[0] = dup2(af0.x); ad[1] = dup2(af0.y); ad[2] = dup2(af0.z); ad[3] = dup2(af0.w);
            ad[4] = dup2(af1.x); ad[5] = dup2(af1.y); ad[6] = dup2(af1.z); ad[7] = dup2(af1.w);
            #pragma unroll
            for (int i = 0; i < 8; i++) {
                fma2(acc[i][0], ad[i], b01.x);
                fma2(acc[i][1], ad[i], b01.y);
                fma2(acc[i][2], ad[i], b23.x);
                fma2(acc[i][3], ad[i], b23.y);
            }
        }
    }

    float wb[8];
    #pragma unroll
    for (int j = 0; j < 8; j++) wb[j] = Wb[n0 + tx * 8 + j];

    #pragma unroll
    for (int i = 0; i < 8; i++) {
        float o[8];
        #pragma unroll
        for (int jp = 0; jp < 4; jp++) {
            float lo, hi; unpack2(acc[i][jp], lo, hi);
            o[jp * 2]     = lo + wb[jp * 2];
            o[jp * 2 + 1] = hi + wb[jp * 2 + 1];
        }
        size_t row = (size_t)(m0 + ty * 8 + i);
        float4* dst = (float4*)&g_wx[row * FOURH + n0 + tx * 8];
        dst[0] = make_float4(o[0], o[1], o[2], o[3]);
        dst[1] = make_float4(o[4], o[5], o[6], o[7]);
    }
}

// =====================================================================
// Kernel 2: persistent recurrent sLSTM. 128 blocks x 512 threads (16 warps).
// Block b owns hidden units [4b, 4b+4).
// Warp w: gate g = w>>2, batch-pair bp = w&3 (batches 2bp, 2bp+1).
// Per warp: 4 rows x 2 batches, full 512-col dots. Registers: acc 16, u 32.
// =====================================================================
__global__ void __launch_bounds__(512) lstm_rec_kernel(
    const float* __restrict__ Uw, const float* __restrict__ Ub,
    const float* __restrict__ alpha, float* __restrict__ out)
{
    __shared__ __align__(16) float h_s[Bb][Hh];   // 16 KB staged hidden state
    __shared__ float z_s[16][32];                 // per-warp reduced dots

    const int tid  = threadIdx.x;
    const int w    = tid >> 5;
    const int lane = tid & 31;
    const int g    = w >> 2;       // gate
    const int bp   = w & 3;        // batch pair (batches 2bp, 2bp+1)
    const int blk  = blockIdx.x;
    const int j0   = blk * 4;

    // U_w rows register-resident: warp (g,bp) holds rows j0..j0+3 of gate g;
    // lane owns cols {4*lane + 128*q : q=0..3}.
    ulonglong2 u[4][4];
    #pragma unroll
    for (int r = 0; r < 4; r++)
        #pragma unroll
        for (int q = 0; q < 4; q++)
            u[r][q] = *(const ulonglong2*)&Uw[(size_t)(g * Hh + j0 + r) * Hh + 128 * q + 4 * lane];

    const int bb = lane & 7;       // batch for finalize lane
    const int jl = lane >> 3;      // local hidden unit for finalize lane
    float c_st = 0.f, alpha_r = 0.f;
    float ub_r[4] = {0.f, 0.f, 0.f, 0.f};
    if (w == 0) {
        #pragma unroll
        for (int gg = 0; gg < 4; gg++) ub_r[gg] = Ub[gg * Hh + j0 + jl];
        alpha_r = alpha[j0 + jl];
    }

    // publish h0 = 0 (warp 0 zeroes this block's 32-float slice)
    if (w == 0) {
        g_h[0][blk * 32 + lane] = 0.f;
        __syncwarp();
        if (lane == 0) bar_arrive_release();
    }
    __syncthreads();

    unsigned target = GRID_R;
    for (int t = 0; t < Tt; ++t) {
        // prefetch Wx_t (independent of h -> overlaps barrier wait + DRAM latency)
        float wx[4];
        if (w == 0) {
            const float* wp = &g_wx[((size_t)bb * Tt + t) * FOURH + j0 + jl];
            #pragma unroll
            for (int gg = 0; gg < 4; gg++) wx[gg] = __ldg(wp + gg * Hh);
        }

        // grid barrier: acquire-poll on single counter (tid 0 only)
        if (tid == 0) {
            int spins = 0;
            while (bar_peek_acquire() < target) {
                if (++spins > 64) { __nanosleep(64); }
            }
        }
        __syncthreads();

        // stage h_t into smem (L2-only loads; keep g_h out of L1)
        {
            const float4* src = (const float4*)g_h[t & 1];
            float4* dst = (float4*)&h_s[0][0];
            dst[tid]       = __ldcg(&src[tid]);
            dst[tid + 512] = __ldcg(&src[tid + 512]);
        }
        __syncthreads();

        // dots: 4 rows x 2 batches over full 512 cols (register accumulators only)
        u64 acc[4][2];
        #pragma unroll
        for (int r = 0; r < 4; r++) { acc[r][0] = 0ull; acc[r][1] = 0ull; }
        const int b0 = 2 * bp;
        #pragma unroll
        for (int bi = 0; bi < 2; bi++) {
            #pragma unroll
            for (int q = 0; q < 4; q++) {
                ulonglong2 h2 = *(const ulonglong2*)&h_s[b0 + bi][128 * q + 4 * lane];
                #pragma unroll
                for (int r = 0; r < 4; r++) {
                    fma2(acc[r][bi], u[r][q].x, h2.x);
                    fma2(acc[r][bi], u[r][q].y, h2.y);
                }
            }
        }

        // collapse pair halves -> v[m], m = 2*r + bi  (8 values per lane)
        float v[8];
        #pragma unroll
        for (int r = 0; r < 4; r++)
            #pragma unroll
            for (int bi = 0; bi < 2; bi++) {
                float lo, hi; unpack2(acc[r][bi], lo, hi);
                v[2 * r + bi] = lo + hi;
            }

        // 9-shfl multi-value butterfly: fold 8->4 (d16), 4->2 (d8), 2->1 (d4),
        // then scalar adds d2, d1. Lane L ends with total of m = 4*b4+2*b3+b2.
        {
            const bool up16 = (lane & 16) != 0;
            #pragma unroll
            for (int i = 0; i < 4; i++) {
                float a = v[i], b = v[i + 4];
                float mine = up16 ? b : a, oth = up16 ? a : b;
                v[i] = mine + __shfl_xor_sync(0xffffffffu, oth, 16);
            }
            const bool up8 = (lane & 8) != 0;
            #pragma unroll
            for (int i = 0; i < 2; i++) {
                float a = v[i], b = v[i + 2];
                float mine = up8 ? b : a, oth = up8 ? a : b;
                v[i] = mine + __shfl_xor_sync(0xffffffffu, oth, 8);
            }
            const bool up4 = (lane & 4) != 0;
            {
                float a = v[0], b = v[1];
                float mine = up4 ? b : a, oth = up4 ? a : b;
                v[0] = mine + __shfl_xor_sync(0xffffffffu, oth, 4);
            }
            v[0] += __shfl_xor_sync(0xffffffffu, v[0], 2);
            v[0] += __shfl_xor_sync(0xffffffffu, v[0], 1);
        }
        z_s[w][lane] = v[0];
        __syncthreads();

        // gate math + state update (warp 0; c lives in registers)
        if (w == 0) {
            // for gate g: source warp (g, bp=bb>>1), value m = 2*jl + (bb&1),
            // copy at lane m*4 + bp  (bank-conflict-free by construction)
            float z[4];
            #pragma unroll
            for (int gg = 0; gg < 4; gg++) {
                int wsrc = gg * 4 + (bb >> 1);
                int lsrc = (2 * jl + (bb & 1)) * 4 + (bb >> 1);
                z[gg] = z_s[wsrc][lsrc] + wx[gg] + ub_r[gg];
            }
            float ig = sigm_f(z[0]), fg = sigm_f(z[1]), og = sigm_f(z[2]);
            float gg = tanh_f(z[3]);
            c_st = alpha_r * (fg * c_st + ig * gg);
            float hv = og * tanh_f(c_st);

            // publish h_{t+1}, then arrive (release orders the publish)
            g_h[(t + 1) & 1][bb * Hh + j0 + jl] = hv;
            __syncwarp();
            if (lane == 0) bar_arrive_release();

            // off-critical-path stores (kernel-end fence covers visibility)
            out[((size_t)bb * Tt + t) * Hh + j0 + jl] = hv;
            if (t == Tt - 1) {
                out[(size_t)Bb * Tt * Hh + bb * Hh + j0 + jl] = hv;                      // final h
                out[(size_t)Bb * Tt * Hh + (size_t)Bb * Hh + bb * Hh + j0 + jl] = c_st;  // final c
            }
        }
        target += GRID_R;
    }

    // self-reset barrier so subsequent graph replays start clean
    if (tid == 0) {
        unsigned old = atomicAdd(&g_bar, 1u);
        if (old == (unsigned)(GRID_R * (Tt + 2) - 1))
            atomicExch(&g_bar, 0u);
    }
}

// =====================================================================
extern "C" void kernel_launch(void* const* d_in, const int* in_sizes, int n_in,
                              void* d_out, int out_size)
{
    const float* x     = (const float*)d_in[0];
    const float* Ww    = (const float*)d_in[1];
    const float* Wb    = (const float*)d_in[2];
    const float* Uw    = (const float*)d_in[3];
    const float* Ub    = (const float*)d_in[4];
    const float* alpha = (const float*)d_in[5];
    float* out = (float*)d_out;

    dim3 ggrid(FOURH / 128, (Bb * Tt) / 128);   // 16 x 128
    gemm_wx_kernel<<<ggrid, 256>>>(x, Ww, Wb);
    lstm_rec_kernel<<<GRID_R, 512>>>(Uw, Ub, alpha, out);
}